// round 13
// baseline (speedup 1.0000x reference)
#include <cuda_runtime.h>
#include <cuda_fp16.h>

#define DD 160
#define HH 160
#define WW 160
#define NB 2
#define HW_ (HH * WW)
#define HW2 (HW_ / 2)
#define DHW_ (DD * HH * WW)          // 4,096,000
#define DHW2 (DHW_ / 2)
#define NVOX (NB * DHW_)             // 8,192,000
#define DCH 4
#define DL  (DD / DCH)               // 40
#define HCH 5
#define HL  (HH / HCH)               // 32
#define NPART 1000                   // passH blocks

#define G0c 0.0125602f
#define G1c 0.0788279f
#define G2c 0.2372961f
#define G3c 0.3426315f

typedef unsigned long long u64;

__device__ __forceinline__ float gk(int k) {
    constexpr float g[7] = {G0c, G1c, G2c, G3c, G2c, G1c, G0c};
    return g[k];
}
__device__ __forceinline__ u64 pk(float lo, float hi) {
    u64 r; asm("mov.b64 %0, {%1, %2};" : "=l"(r) : "f"(lo), "f"(hi)); return r;
}
__device__ __forceinline__ float2 upk(u64 v) {
    float2 r; asm("mov.b64 {%0, %1}, %2;" : "=f"(r.x), "=f"(r.y) : "l"(v)); return r;
}
__device__ __forceinline__ u64 fma2(u64 a, u64 b, u64 c) {
    u64 d; asm("fma.rn.f32x2 %0, %1, %2, %3;" : "=l"(d) : "l"(a), "l"(b), "l"(c)); return d;
}
__device__ __forceinline__ u64 mul2(u64 a, u64 b) {
    u64 d; asm("mul.rn.f32x2 %0, %1, %2;" : "=l"(d) : "l"(a), "l"(b)); return d;
}
__device__ __forceinline__ u64 add2(u64 a, u64 b) {
    u64 d; asm("add.rn.f32x2 %0, %1, %2;" : "=l"(d) : "l"(a), "l"(b)); return d;
}
__device__ __forceinline__ unsigned h2u(__half2 h) {
    return *reinterpret_cast<unsigned*>(&h);
}

// zero-padding valid-weight factor per axis
__device__ __forceinline__ float bfac(int i) {
    float f = 1.f;
    if (i < 3)   f -= (i == 2 ? G0c : (i == 1 ? (G0c + G1c) : (G0c + G1c + G2c)));
    if (i > 156) f -= (i == 157 ? G0c : (i == 158 ? (G0c + G1c) : (G0c + G1c + G2c)));
    return f;
}

// g_buf : planar [vol=f*NB+n][d][h][w] fp16 (passW out / passD in)
// g_buf2: field-interleaved [n][d][h][f][80*half2] fp16 (passD out / passH in)
__device__ __half g_buf[10u * DHW_];
__device__ __half g_buf2[10u * DHW_];
__device__ float g_partials[NPART];
__device__ int g_ctr;

// ---------------------------------------------------------------------------
// passW: 7-tap W-conv of the 5 shifted fields {q,r,q2,r2,qr}, q=p-1/2.
// Thread owns an 8-wide w-octet. Scatter form with FFMA-imm. (R12-proven)
// ---------------------------------------------------------------------------
__global__ void __launch_bounds__(256) passW(const float* __restrict__ p,
                                             const float* __restrict__ t) {
    int tid = blockIdx.x * blockDim.x + threadIdx.x;   // 1,024,000
    int oct = tid % 20;
    int rem = tid / 20;
    int h   = rem % HH;
    int rm2 = rem / HH;
    int d   = rm2 % DD;
    int n   = rm2 / DD;
    int w0  = oct * 8;

    long rb = (long)n * DHW_ + ((long)d * HH + h) * WW + w0;
    const float4* p4 = (const float4*)(p + rb - 4);
    const float4* t4 = (const float4*)(t + rb - 4);
    const float4 z4 = {0.f, 0.f, 0.f, 0.f};

    float4 a0 = (oct > 0)  ? p4[0] : z4;
    float4 a1 = p4[1];
    float4 a2 = p4[2];
    float4 a3 = (oct < 19) ? p4[3] : z4;
    float4 b0 = (oct > 0)  ? t4[0] : z4;
    float4 b1 = t4[1];
    float4 b2 = t4[2];
    float4 b3 = (oct < 19) ? t4[3] : z4;

    float q[16], r[16];
    q[0]=0.f;       q[1]=a0.y-0.5f; q[2]=a0.z-0.5f; q[3]=a0.w-0.5f;
    q[4]=a1.x-0.5f; q[5]=a1.y-0.5f; q[6]=a1.z-0.5f; q[7]=a1.w-0.5f;
    q[8]=a2.x-0.5f; q[9]=a2.y-0.5f; q[10]=a2.z-0.5f; q[11]=a2.w-0.5f;
    q[12]=a3.x-0.5f; q[13]=a3.y-0.5f; q[14]=a3.z-0.5f; q[15]=0.f;
    r[0]=0.f;       r[1]=b0.y-0.5f; r[2]=b0.z-0.5f; r[3]=b0.w-0.5f;
    r[4]=b1.x-0.5f; r[5]=b1.y-0.5f; r[6]=b1.z-0.5f; r[7]=b1.w-0.5f;
    r[8]=b2.x-0.5f; r[9]=b2.y-0.5f; r[10]=b2.z-0.5f; r[11]=b2.w-0.5f;
    r[12]=b3.x-0.5f; r[13]=b3.y-0.5f; r[14]=b3.z-0.5f; r[15]=0.f;

    if (oct == 0)  { q[1]=q[2]=q[3]=0.f;    r[1]=r[2]=r[3]=0.f; }
    if (oct == 19) { q[12]=q[13]=q[14]=0.f; r[12]=r[13]=r[14]=0.f; }

    float c0[8], c1[8], c2[8], c3[8], c4[8];
#pragma unroll
    for (int j = 0; j < 8; ++j) { c0[j]=0.f; c1[j]=0.f; c2[j]=0.f; c3[j]=0.f; c4[j]=0.f; }

#pragma unroll
    for (int i = 1; i < 15; ++i) {
        float qi = q[i], ri = r[i];
        float qq = qi * qi, rr = ri * ri, pr = qi * ri;
#pragma unroll
        for (int j = 0; j < 8; ++j) {
            const int k = i - 1 - j;
            if (k >= 0 && k < 7) {
                const float g = gk(k);
                c0[j] = fmaf(g, qi, c0[j]);
                c1[j] = fmaf(g, ri, c1[j]);
                c2[j] = fmaf(g, qq, c2[j]);
                c3[j] = fmaf(g, rr, c3[j]);
                c4[j] = fmaf(g, pr, c4[j]);
            }
        }
    }

    long ob = rb / 8;
    uint4* outv = (uint4*)g_buf;
    {
        uint4 v;
        v.x = h2u(__floats2half2_rn(c0[0], c0[1]));
        v.y = h2u(__floats2half2_rn(c0[2], c0[3]));
        v.z = h2u(__floats2half2_rn(c0[4], c0[5]));
        v.w = h2u(__floats2half2_rn(c0[6], c0[7]));
        outv[(long)(0 * NB) * (DHW_ / 8) + ob] = v;
        v.x = h2u(__floats2half2_rn(c1[0], c1[1]));
        v.y = h2u(__floats2half2_rn(c1[2], c1[3]));
        v.z = h2u(__floats2half2_rn(c1[4], c1[5]));
        v.w = h2u(__floats2half2_rn(c1[6], c1[7]));
        outv[(long)(1 * NB) * (DHW_ / 8) + ob] = v;
        v.x = h2u(__floats2half2_rn(c2[0], c2[1]));
        v.y = h2u(__floats2half2_rn(c2[2], c2[3]));
        v.z = h2u(__floats2half2_rn(c2[4], c2[5]));
        v.w = h2u(__floats2half2_rn(c2[6], c2[7]));
        outv[(long)(2 * NB) * (DHW_ / 8) + ob] = v;
        v.x = h2u(__floats2half2_rn(c3[0], c3[1]));
        v.y = h2u(__floats2half2_rn(c3[2], c3[3]));
        v.z = h2u(__floats2half2_rn(c3[4], c3[5]));
        v.w = h2u(__floats2half2_rn(c3[6], c3[7]));
        outv[(long)(3 * NB) * (DHW_ / 8) + ob] = v;
        v.x = h2u(__floats2half2_rn(c4[0], c4[1]));
        v.y = h2u(__floats2half2_rn(c4[2], c4[3]));
        v.z = h2u(__floats2half2_rn(c4[4], c4[5]));
        v.w = h2u(__floats2half2_rn(c4[6], c4[7]));
        outv[(long)(4 * NB) * (DHW_ / 8) + ob] = v;
    }
}

// ---------------------------------------------------------------------------
// passD: streaming 7-tap D-conv in HFMA2, 8 voxels (uint4) per thread-step.
// Reads planar g_buf; writes field-interleaved g_buf2. (R12-proven)
// ---------------------------------------------------------------------------
__global__ void __launch_bounds__(256) passD() {
    int tid = blockIdx.x * blockDim.x + threadIdx.x;   // 128,000
    int wq  = tid % 20;
    int rem = tid / 20;
    int ci  = rem % DCH;
    int rm2 = rem / DCH;
    int h   = rm2 % HH;
    int vol = rm2 / HH;
    int d0  = ci * DL;
    int f   = vol >> 1;
    int n   = vol & 1;

    const uint4* src = (const uint4*)g_buf + (long)vol * (DHW_ / 8) + (long)h * 20 + wq;
    uint4* dst = (uint4*)g_buf2 + (((long)n * DD + d0) * HH + h) * 100 + f * 20 + wq;
    const int DS  = HW_ / 8;
    const int DSO = HH * 100;

    const __half2 Z = __float2half2_rn(0.f);
    const __half2 G0h = __float2half2_rn(G0c), G1h = __float2half2_rn(G1c);
    const __half2 G2h = __float2half2_rn(G2c), G3h = __float2half2_rn(G3c);

    __half2 w0[7], w1[7], w2[7], w3[7];
#pragma unroll
    for (int k = 0; k < 7; ++k) {
        int dd = d0 - 3 + k;
        if (dd >= 0 && dd < DD) {
            uint4 v = src[(long)dd * DS];
            w0[k] = *(__half2*)&v.x; w1[k] = *(__half2*)&v.y;
            w2[k] = *(__half2*)&v.z; w3[k] = *(__half2*)&v.w;
        } else { w0[k] = Z; w1[k] = Z; w2[k] = Z; w3[k] = Z; }
    }

    const uint4* sp = src + (long)(d0 + 4) * DS;

#pragma unroll 4
    for (int i = 0; i < DL; ++i) {
        int dn = d0 + i + 4;
        __half2 n0 = Z, n1 = Z, n2 = Z, n3 = Z;
        if (dn < DD) {
            uint4 v = *sp;
            n0 = *(__half2*)&v.x; n1 = *(__half2*)&v.y;
            n2 = *(__half2*)&v.z; n3 = *(__half2*)&v.w;
        }
        __half2 y0 = __hmul2(G0h, w0[0]);
        __half2 y1 = __hmul2(G0h, w1[0]);
        __half2 y2 = __hmul2(G0h, w2[0]);
        __half2 y3 = __hmul2(G0h, w3[0]);
        y0 = __hfma2(G1h, w0[1], y0); y1 = __hfma2(G1h, w1[1], y1);
        y2 = __hfma2(G1h, w2[1], y2); y3 = __hfma2(G1h, w3[1], y3);
        y0 = __hfma2(G2h, w0[2], y0); y1 = __hfma2(G2h, w1[2], y1);
        y2 = __hfma2(G2h, w2[2], y2); y3 = __hfma2(G2h, w3[2], y3);
        y0 = __hfma2(G3h, w0[3], y0); y1 = __hfma2(G3h, w1[3], y1);
        y2 = __hfma2(G3h, w2[3], y2); y3 = __hfma2(G3h, w3[3], y3);
        y0 = __hfma2(G2h, w0[4], y0); y1 = __hfma2(G2h, w1[4], y1);
        y2 = __hfma2(G2h, w2[4], y2); y3 = __hfma2(G2h, w3[4], y3);
        y0 = __hfma2(G1h, w0[5], y0); y1 = __hfma2(G1h, w1[5], y1);
        y2 = __hfma2(G1h, w2[5], y2); y3 = __hfma2(G1h, w3[5], y3);
        y0 = __hfma2(G0h, w0[6], y0); y1 = __hfma2(G0h, w1[6], y1);
        y2 = __hfma2(G0h, w2[6], y2); y3 = __hfma2(G0h, w3[6], y3);
        uint4 o;
        o.x = h2u(y0); o.y = h2u(y1); o.z = h2u(y2); o.w = h2u(y3);
        *dst = o;
#pragma unroll
        for (int k = 0; k < 6; ++k) {
            w0[k] = w0[k + 1]; w1[k] = w1[k + 1];
            w2[k] = w2[k + 1]; w3[k] = w3[k + 1];
        }
        w0[6] = n0; w1[6] = n1; w2[6] = n2; w3[6] = n3;
        sp += DS; dst += DSO;
    }
}

// ---------------------------------------------------------------------------
// passH: streaming 7-tap H-conv (HFMA2) with depth-3 row prefetch + exact
// border reconstruction + SSIM (f32x2) + block reduce + last-block reduce.
// Thread = (n, d, w-pair, h-chunk of 32) -> 31% priming amplification.
// ---------------------------------------------------------------------------
__global__ void __launch_bounds__(128, 5) passH(float* __restrict__ out) {
    int tid = blockIdx.x * blockDim.x + threadIdx.x;   // 128,000 exactly
    int wp  = tid % 80;
    int rem = tid / 80;
    int ci  = rem % HCH;
    int rm2 = rem / HCH;
    int d   = rm2 % DD;
    int n   = rm2 / DD;
    int h0  = ci * HL;
    int w2  = 2 * wp;

    const __half2 Z = __float2half2_rn(0.f);
    const __half2 G0h = __float2half2_rn(G0c), G1h = __float2half2_rn(G1c);
    const __half2 G2h = __float2half2_rn(G2c), G3h = __float2half2_rn(G3c);
    const u64 K05 = pk(0.5f,0.5f), Kn025 = pk(-0.25f,-0.25f), K2 = pk(2.f,2.f);
    const u64 KC1 = pk(1e-4f,1e-4f), KC2 = pk(9e-4f,9e-4f), Kn1 = pk(-1.f,-1.f);

    float bd = bfac(d);
    u64 wwp = pk(bd * bfac(w2), bd * bfac(w2 + 1));

    const __half2* base = (const __half2*)g_buf2 +
                          (((long)n * DD + d) * HH) * 400 + wp;

    __half2 win[5][7];
#pragma unroll
    for (int k = 0; k < 7; ++k) {
        int row = h0 - 3 + k;
        bool v = (row >= 0) && (row < HH);
        const __half2* rp = base + (long)(v ? row : 0) * 400;
#pragma unroll
        for (int f = 0; f < 5; ++f)
            win[f][k] = v ? rp[f * 80] : Z;
    }

    // depth-3 prefetch: P1=row h0+4, P2=h0+5, P3=h0+6
    __half2 P1[5], P2[5], P3[5];
    {
        bool v1 = (h0 + 4 < HH), v2 = (h0 + 5 < HH), v3 = (h0 + 6 < HH);
        const __half2* r1 = base + (long)(v1 ? h0 + 4 : 0) * 400;
        const __half2* r2 = base + (long)(v2 ? h0 + 5 : 0) * 400;
        const __half2* r3 = base + (long)(v3 ? h0 + 6 : 0) * 400;
#pragma unroll
        for (int f = 0; f < 5; ++f) {
            P1[f] = v1 ? r1[f * 80] : Z;
            P2[f] = v2 ? r2[f * 80] : Z;
            P3[f] = v3 ? r3[f * 80] : Z;
        }
    }

    float acc_ssim = 0.f;

#pragma unroll 4
    for (int i = 0; i < HL; ++i) {
        int h = h0 + i;

        u64 c[5];
#pragma unroll
        for (int f = 0; f < 5; ++f) {
            __half2 y = __hmul2(G0h, win[f][0]);
            y = __hfma2(G1h, win[f][1], y);
            y = __hfma2(G2h, win[f][2], y);
            y = __hfma2(G3h, win[f][3], y);
            y = __hfma2(G2h, win[f][4], y);
            y = __hfma2(G1h, win[f][5], y);
            y = __hfma2(G0h, win[f][6], y);
            float2 cf = __half22float2(y);
            c[f] = pk(cf.x, cf.y);
        }

        float bh = bfac(h);
        u64 W2  = mul2(wwp, pk(bh, bh));
        u64 mu1 = fma2(W2, K05, c[0]);
        u64 mu2 = fma2(W2, K05, c[1]);
        u64 Ep2 = fma2(W2, Kn025, add2(c[2], mu1));
        u64 Et2 = fma2(W2, Kn025, add2(c[3], mu2));
        u64 Ept = fma2(add2(mu1, mu2), K05, fma2(W2, Kn025, c[4]));
        u64 mu1s = mul2(mu1, mu1), mu2s = mul2(mu2, mu2), mu12 = mul2(mu1, mu2);
        u64 s1  = fma2(mu1s, Kn1, Ep2);
        u64 s2  = fma2(mu2s, Kn1, Et2);
        u64 s12 = fma2(mu12, Kn1, Ept);
        u64 num = mul2(fma2(mu12, K2, KC1), fma2(s12, K2, KC2));
        u64 den = mul2(add2(add2(mu1s, mu2s), KC1), add2(add2(s1, s2), KC2));
        float2 nf = upk(num), df = upk(den);
        acc_ssim += __fdividef(nf.x, df.x) + __fdividef(nf.y, df.y);

        // shift window; rotate prefetch pipeline; issue load for row h+7
        bool v = (h + 7 < HH);
        const __half2* rp = base + (long)(v ? h + 7 : 0) * 400;
#pragma unroll
        for (int f = 0; f < 5; ++f) {
#pragma unroll
            for (int k = 0; k < 6; ++k) win[f][k] = win[f][k + 1];
            win[f][6] = P1[f];
            P1[f] = P2[f];
            P2[f] = P3[f];
            P3[f] = v ? rp[f * 80] : Z;
        }
    }

    __shared__ float sred[128];
    __shared__ bool is_last;
    int lt = threadIdx.x;
    sred[lt] = acc_ssim;
    __syncthreads();
    for (int s = 64; s > 0; s >>= 1) {
        if (lt < s) sred[lt] += sred[lt + s];
        __syncthreads();
    }
    if (lt == 0) {
        g_partials[blockIdx.x] = sred[0];
        __threadfence();
        int v = atomicAdd(&g_ctr, 1);
        is_last = (v == (int)gridDim.x - 1);
    }
    __syncthreads();

    if (is_last) {
        __shared__ double sm[128];
        double acc = 0.0;
        for (int i = lt; i < NPART; i += 128) acc += (double)g_partials[i];
        sm[lt] = acc;
        __syncthreads();
        for (int s = 64; s > 0; s >>= 1) {
            if (lt < s) sm[lt] += sm[lt + s];
            __syncthreads();
        }
        if (lt == 0) {
            out[0] = 1.f - (float)(sm[0] / (double)NVOX);
            g_ctr = 0;   // reset for next graph replay
        }
    }
}

extern "C" void kernel_launch(void* const* d_in, const int* in_sizes, int n_in,
                              void* d_out, int out_size) {
    const float* p = (const float*)d_in[0];
    const float* t = (const float*)d_in[1];
    float* out = (float*)d_out;

    passW<<<4000, 256>>>(p, t);     // 1,024,000 threads
    passD<<<500, 256>>>();          //   128,000 threads (8 voxels/step)
    passH<<<NPART, 128>>>(out);     //   128,000 threads + folded reduce
}

// round 14
// speedup vs baseline: 1.0551x; 1.0551x over previous
#include <cuda_runtime.h>
#include <cuda_fp16.h>

#define DD 160
#define HH 160
#define WW 160
#define NB 2
#define HW_ (HH * WW)
#define HW2 (HW_ / 2)
#define DHW_ (DD * HH * WW)          // 4,096,000
#define DHW2 (DHW_ / 2)
#define NVOX (NB * DHW_)             // 8,192,000
#define DCH 4
#define DL  (DD / DCH)               // 40
#define HCH 10
#define HL  (HH / HCH)               // 16
#define NPART 2000                   // passH blocks

#define G0c 0.0125602f
#define G1c 0.0788279f
#define G2c 0.2372961f
#define G3c 0.3426315f

typedef unsigned long long u64;

__device__ __forceinline__ float gk(int k) {
    constexpr float g[7] = {G0c, G1c, G2c, G3c, G2c, G1c, G0c};
    return g[k];
}
__device__ __forceinline__ u64 pk(float lo, float hi) {
    u64 r; asm("mov.b64 %0, {%1, %2};" : "=l"(r) : "f"(lo), "f"(hi)); return r;
}
__device__ __forceinline__ float2 upk(u64 v) {
    float2 r; asm("mov.b64 {%0, %1}, %2;" : "=f"(r.x), "=f"(r.y) : "l"(v)); return r;
}
__device__ __forceinline__ u64 fma2(u64 a, u64 b, u64 c) {
    u64 d; asm("fma.rn.f32x2 %0, %1, %2, %3;" : "=l"(d) : "l"(a), "l"(b), "l"(c)); return d;
}
__device__ __forceinline__ u64 mul2(u64 a, u64 b) {
    u64 d; asm("mul.rn.f32x2 %0, %1, %2;" : "=l"(d) : "l"(a), "l"(b)); return d;
}
__device__ __forceinline__ u64 add2(u64 a, u64 b) {
    u64 d; asm("add.rn.f32x2 %0, %1, %2;" : "=l"(d) : "l"(a), "l"(b)); return d;
}
__device__ __forceinline__ unsigned h2u(__half2 h) {
    return *reinterpret_cast<unsigned*>(&h);
}

// zero-padding valid-weight factor per axis
__device__ __forceinline__ float bfac(int i) {
    float f = 1.f;
    if (i < 3)   f -= (i == 2 ? G0c : (i == 1 ? (G0c + G1c) : (G0c + G1c + G2c)));
    if (i > 156) f -= (i == 157 ? G0c : (i == 158 ? (G0c + G1c) : (G0c + G1c + G2c)));
    return f;
}

// g_buf : planar [vol=f*NB+n][d][h][w] fp16 (passW out / passD in)
// g_buf2: field-interleaved [n][d][h][f][80*half2] fp16 (passD out / passH in)
__device__ __half g_buf[10u * DHW_];
__device__ __half g_buf2[10u * DHW_];
__device__ float g_partials[NPART];
__device__ int g_ctr;

// ---------------------------------------------------------------------------
// passW: 7-tap W-conv of the 5 shifted fields {q,r,q2,r2,qr}, q=p-1/2.
// Thread owns an 8-wide w-octet. Scatter form with FFMA-imm. (R12-proven)
// ---------------------------------------------------------------------------
__global__ void __launch_bounds__(256) passW(const float* __restrict__ p,
                                             const float* __restrict__ t) {
    int tid = blockIdx.x * blockDim.x + threadIdx.x;   // 1,024,000
    int oct = tid % 20;
    int rem = tid / 20;
    int h   = rem % HH;
    int rm2 = rem / HH;
    int d   = rm2 % DD;
    int n   = rm2 / DD;
    int w0  = oct * 8;

    long rb = (long)n * DHW_ + ((long)d * HH + h) * WW + w0;
    const float4* p4 = (const float4*)(p + rb - 4);
    const float4* t4 = (const float4*)(t + rb - 4);
    const float4 z4 = {0.f, 0.f, 0.f, 0.f};

    float4 a0 = (oct > 0)  ? p4[0] : z4;
    float4 a1 = p4[1];
    float4 a2 = p4[2];
    float4 a3 = (oct < 19) ? p4[3] : z4;
    float4 b0 = (oct > 0)  ? t4[0] : z4;
    float4 b1 = t4[1];
    float4 b2 = t4[2];
    float4 b3 = (oct < 19) ? t4[3] : z4;

    float q[16], r[16];
    q[0]=0.f;       q[1]=a0.y-0.5f; q[2]=a0.z-0.5f; q[3]=a0.w-0.5f;
    q[4]=a1.x-0.5f; q[5]=a1.y-0.5f; q[6]=a1.z-0.5f; q[7]=a1.w-0.5f;
    q[8]=a2.x-0.5f; q[9]=a2.y-0.5f; q[10]=a2.z-0.5f; q[11]=a2.w-0.5f;
    q[12]=a3.x-0.5f; q[13]=a3.y-0.5f; q[14]=a3.z-0.5f; q[15]=0.f;
    r[0]=0.f;       r[1]=b0.y-0.5f; r[2]=b0.z-0.5f; r[3]=b0.w-0.5f;
    r[4]=b1.x-0.5f; r[5]=b1.y-0.5f; r[6]=b1.z-0.5f; r[7]=b1.w-0.5f;
    r[8]=b2.x-0.5f; r[9]=b2.y-0.5f; r[10]=b2.z-0.5f; r[11]=b2.w-0.5f;
    r[12]=b3.x-0.5f; r[13]=b3.y-0.5f; r[14]=b3.z-0.5f; r[15]=0.f;

    if (oct == 0)  { q[1]=q[2]=q[3]=0.f;    r[1]=r[2]=r[3]=0.f; }
    if (oct == 19) { q[12]=q[13]=q[14]=0.f; r[12]=r[13]=r[14]=0.f; }

    float c0[8], c1[8], c2[8], c3[8], c4[8];
#pragma unroll
    for (int j = 0; j < 8; ++j) { c0[j]=0.f; c1[j]=0.f; c2[j]=0.f; c3[j]=0.f; c4[j]=0.f; }

#pragma unroll
    for (int i = 1; i < 15; ++i) {
        float qi = q[i], ri = r[i];
        float qq = qi * qi, rr = ri * ri, pr = qi * ri;
#pragma unroll
        for (int j = 0; j < 8; ++j) {
            const int k = i - 1 - j;
            if (k >= 0 && k < 7) {
                const float g = gk(k);
                c0[j] = fmaf(g, qi, c0[j]);
                c1[j] = fmaf(g, ri, c1[j]);
                c2[j] = fmaf(g, qq, c2[j]);
                c3[j] = fmaf(g, rr, c3[j]);
                c4[j] = fmaf(g, pr, c4[j]);
            }
        }
    }

    long ob = rb / 8;
    uint4* outv = (uint4*)g_buf;
    {
        uint4 v;
        v.x = h2u(__floats2half2_rn(c0[0], c0[1]));
        v.y = h2u(__floats2half2_rn(c0[2], c0[3]));
        v.z = h2u(__floats2half2_rn(c0[4], c0[5]));
        v.w = h2u(__floats2half2_rn(c0[6], c0[7]));
        outv[(long)(0 * NB) * (DHW_ / 8) + ob] = v;
        v.x = h2u(__floats2half2_rn(c1[0], c1[1]));
        v.y = h2u(__floats2half2_rn(c1[2], c1[3]));
        v.z = h2u(__floats2half2_rn(c1[4], c1[5]));
        v.w = h2u(__floats2half2_rn(c1[6], c1[7]));
        outv[(long)(1 * NB) * (DHW_ / 8) + ob] = v;
        v.x = h2u(__floats2half2_rn(c2[0], c2[1]));
        v.y = h2u(__floats2half2_rn(c2[2], c2[3]));
        v.z = h2u(__floats2half2_rn(c2[4], c2[5]));
        v.w = h2u(__floats2half2_rn(c2[6], c2[7]));
        outv[(long)(2 * NB) * (DHW_ / 8) + ob] = v;
        v.x = h2u(__floats2half2_rn(c3[0], c3[1]));
        v.y = h2u(__floats2half2_rn(c3[2], c3[3]));
        v.z = h2u(__floats2half2_rn(c3[4], c3[5]));
        v.w = h2u(__floats2half2_rn(c3[6], c3[7]));
        outv[(long)(3 * NB) * (DHW_ / 8) + ob] = v;
        v.x = h2u(__floats2half2_rn(c4[0], c4[1]));
        v.y = h2u(__floats2half2_rn(c4[2], c4[3]));
        v.z = h2u(__floats2half2_rn(c4[4], c4[5]));
        v.w = h2u(__floats2half2_rn(c4[6], c4[7]));
        outv[(long)(4 * NB) * (DHW_ / 8) + ob] = v;
    }
}

// ---------------------------------------------------------------------------
// passD: streaming 7-tap D-conv in HFMA2, 8 voxels (uint4) per thread-step.
// Reads planar g_buf; writes field-interleaved g_buf2. (R12-proven)
// ---------------------------------------------------------------------------
__global__ void __launch_bounds__(256) passD() {
    int tid = blockIdx.x * blockDim.x + threadIdx.x;   // 128,000
    int wq  = tid % 20;
    int rem = tid / 20;
    int ci  = rem % DCH;
    int rm2 = rem / DCH;
    int h   = rm2 % HH;
    int vol = rm2 / HH;
    int d0  = ci * DL;
    int f   = vol >> 1;
    int n   = vol & 1;

    const uint4* src = (const uint4*)g_buf + (long)vol * (DHW_ / 8) + (long)h * 20 + wq;
    uint4* dst = (uint4*)g_buf2 + (((long)n * DD + d0) * HH + h) * 100 + f * 20 + wq;
    const int DS  = HW_ / 8;
    const int DSO = HH * 100;

    const __half2 Z = __float2half2_rn(0.f);
    const __half2 G0h = __float2half2_rn(G0c), G1h = __float2half2_rn(G1c);
    const __half2 G2h = __float2half2_rn(G2c), G3h = __float2half2_rn(G3c);

    __half2 w0[7], w1[7], w2[7], w3[7];
#pragma unroll
    for (int k = 0; k < 7; ++k) {
        int dd = d0 - 3 + k;
        if (dd >= 0 && dd < DD) {
            uint4 v = src[(long)dd * DS];
            w0[k] = *(__half2*)&v.x; w1[k] = *(__half2*)&v.y;
            w2[k] = *(__half2*)&v.z; w3[k] = *(__half2*)&v.w;
        } else { w0[k] = Z; w1[k] = Z; w2[k] = Z; w3[k] = Z; }
    }

    const uint4* sp = src + (long)(d0 + 4) * DS;

#pragma unroll 4
    for (int i = 0; i < DL; ++i) {
        int dn = d0 + i + 4;
        __half2 n0 = Z, n1 = Z, n2 = Z, n3 = Z;
        if (dn < DD) {
            uint4 v = *sp;
            n0 = *(__half2*)&v.x; n1 = *(__half2*)&v.y;
            n2 = *(__half2*)&v.z; n3 = *(__half2*)&v.w;
        }
        __half2 y0 = __hmul2(G0h, w0[0]);
        __half2 y1 = __hmul2(G0h, w1[0]);
        __half2 y2 = __hmul2(G0h, w2[0]);
        __half2 y3 = __hmul2(G0h, w3[0]);
        y0 = __hfma2(G1h, w0[1], y0); y1 = __hfma2(G1h, w1[1], y1);
        y2 = __hfma2(G1h, w2[1], y2); y3 = __hfma2(G1h, w3[1], y3);
        y0 = __hfma2(G2h, w0[2], y0); y1 = __hfma2(G2h, w1[2], y1);
        y2 = __hfma2(G2h, w2[2], y2); y3 = __hfma2(G2h, w3[2], y3);
        y0 = __hfma2(G3h, w0[3], y0); y1 = __hfma2(G3h, w1[3], y1);
        y2 = __hfma2(G3h, w2[3], y2); y3 = __hfma2(G3h, w3[3], y3);
        y0 = __hfma2(G2h, w0[4], y0); y1 = __hfma2(G2h, w1[4], y1);
        y2 = __hfma2(G2h, w2[4], y2); y3 = __hfma2(G2h, w3[4], y3);
        y0 = __hfma2(G1h, w0[5], y0); y1 = __hfma2(G1h, w1[5], y1);
        y2 = __hfma2(G1h, w2[5], y2); y3 = __hfma2(G1h, w3[5], y3);
        y0 = __hfma2(G0h, w0[6], y0); y1 = __hfma2(G0h, w1[6], y1);
        y2 = __hfma2(G0h, w2[6], y2); y3 = __hfma2(G0h, w3[6], y3);
        uint4 o;
        o.x = h2u(y0); o.y = h2u(y1); o.z = h2u(y2); o.w = h2u(y3);
        *dst = o;
#pragma unroll
        for (int k = 0; k < 6; ++k) {
            w0[k] = w0[k + 1]; w1[k] = w1[k + 1];
            w2[k] = w2[k + 1]; w3[k] = w3[k + 1];
        }
        w0[6] = n0; w1[6] = n1; w2[6] = n2; w3[6] = n3;
        sp += DS; dst += DSO;
    }
}

// ---------------------------------------------------------------------------
// passH: streaming 7-tap H-conv (HFMA2) with depth-2 row prefetch + exact
// border reconstruction + SSIM with ONE divide per voxel-pair + block reduce
// + last-block final reduce. Thread = (n, d, w-pair, h-chunk of 16). (R12
// config; SSIM algebra: mu1^2+mu2^2 = S^2 - 2*mu12, Ep2+Et2 summed directly)
// ---------------------------------------------------------------------------
__global__ void __launch_bounds__(128, 5) passH(float* __restrict__ out) {
    int tid = blockIdx.x * blockDim.x + threadIdx.x;   // 256,000 exactly
    int wp  = tid % 80;
    int rem = tid / 80;
    int ci  = rem % HCH;
    int rm2 = rem / HCH;
    int d   = rm2 % DD;
    int n   = rm2 / DD;
    int h0  = ci * HL;
    int w2  = 2 * wp;

    const __half2 Z = __float2half2_rn(0.f);
    const __half2 G0h = __float2half2_rn(G0c), G1h = __float2half2_rn(G1c);
    const __half2 G2h = __float2half2_rn(G2c), G3h = __float2half2_rn(G3c);
    const u64 K05 = pk(0.5f,0.5f), Kn025 = pk(-0.25f,-0.25f), K2 = pk(2.f,2.f);
    const u64 KC1 = pk(1e-4f,1e-4f), KC2 = pk(9e-4f,9e-4f), Kn1 = pk(-1.f,-1.f);
    const u64 Kn2 = pk(-2.f,-2.f), Kn05 = pk(-0.5f,-0.5f);

    float bd = bfac(d);
    u64 wwp = pk(bd * bfac(w2), bd * bfac(w2 + 1));

    const __half2* base = (const __half2*)g_buf2 +
                          (((long)n * DD + d) * HH) * 400 + wp;

    __half2 win[5][7];
#pragma unroll
    for (int k = 0; k < 7; ++k) {
        int row = h0 - 3 + k;
        bool v = (row >= 0) && (row < HH);
        const __half2* rp = base + (long)(v ? row : 0) * 400;
#pragma unroll
        for (int f = 0; f < 5; ++f)
            win[f][k] = v ? rp[f * 80] : Z;
    }

    // depth-2 prefetch: P1 = row h0+4, P2 = row h0+5
    __half2 P1[5], P2[5];
    {
        bool v1 = (h0 + 4 < HH), v2 = (h0 + 5 < HH);
        const __half2* r1 = base + (long)(v1 ? h0 + 4 : 0) * 400;
        const __half2* r2 = base + (long)(v2 ? h0 + 5 : 0) * 400;
#pragma unroll
        for (int f = 0; f < 5; ++f) {
            P1[f] = v1 ? r1[f * 80] : Z;
            P2[f] = v2 ? r2[f * 80] : Z;
        }
    }

    float acc_ssim = 0.f;

#pragma unroll 4
    for (int i = 0; i < HL; ++i) {
        int h = h0 + i;

        u64 c[5];
#pragma unroll
        for (int f = 0; f < 5; ++f) {
            __half2 y = __hmul2(G0h, win[f][0]);
            y = __hfma2(G1h, win[f][1], y);
            y = __hfma2(G2h, win[f][2], y);
            y = __hfma2(G3h, win[f][3], y);
            y = __hfma2(G2h, win[f][4], y);
            y = __hfma2(G1h, win[f][5], y);
            y = __hfma2(G0h, win[f][6], y);
            float2 cf = __half22float2(y);
            c[f] = pk(cf.x, cf.y);
        }

        float bh = bfac(h);
        u64 W2   = mul2(wwp, pk(bh, bh));
        u64 mu1  = fma2(W2, K05, c[0]);
        u64 mu2  = fma2(W2, K05, c[1]);
        u64 S    = add2(mu1, mu2);                       // mu1+mu2
        u64 mu12 = mul2(mu1, mu2);
        u64 A    = fma2(mu12, Kn2, mul2(S, S));          // mu1^2+mu2^2
        u64 Ept  = fma2(S, K05, fma2(W2, Kn025, c[4]));  // E[pt]
        u64 s12  = fma2(mu12, Kn1, Ept);
        u64 E2   = fma2(W2, Kn05, add2(add2(c[2], c[3]), S));  // Ep2+Et2
        u64 sden = add2(fma2(A, Kn1, E2), KC2);          // s1+s2+C2
        u64 den  = mul2(add2(A, KC1), sden);
        u64 num  = mul2(fma2(mu12, K2, KC1), fma2(s12, K2, KC2));
        float2 nf = upk(num), df = upk(den);
        // one divide for both lanes: n1/d1 + n2/d2 = (n1*d2 + n2*d1)/(d1*d2)
        float tnum = fmaf(nf.x, df.y, nf.y * df.x);
        acc_ssim += __fdividef(tnum, df.x * df.y);

        // shift window, insert P1; P1 <- P2; issue P2 load (row h+6)
        bool v = (h + 6 < HH);
        const __half2* rp = base + (long)(v ? h + 6 : 0) * 400;
#pragma unroll
        for (int f = 0; f < 5; ++f) {
#pragma unroll
            for (int k = 0; k < 6; ++k) win[f][k] = win[f][k + 1];
            win[f][6] = P1[f];
            P1[f] = P2[f];
            P2[f] = v ? rp[f * 80] : Z;
        }
    }

    __shared__ float sred[128];
    __shared__ bool is_last;
    int lt = threadIdx.x;
    sred[lt] = acc_ssim;
    __syncthreads();
    for (int s = 64; s > 0; s >>= 1) {
        if (lt < s) sred[lt] += sred[lt + s];
        __syncthreads();
    }
    if (lt == 0) {
        g_partials[blockIdx.x] = sred[0];
        __threadfence();
        int v = atomicAdd(&g_ctr, 1);
        is_last = (v == (int)gridDim.x - 1);
    }
    __syncthreads();

    if (is_last) {
        __shared__ double sm[128];
        double acc = 0.0;
        for (int i = lt; i < NPART; i += 128) acc += (double)g_partials[i];
        sm[lt] = acc;
        __syncthreads();
        for (int s = 64; s > 0; s >>= 1) {
            if (lt < s) sm[lt] += sm[lt + s];
            __syncthreads();
        }
        if (lt == 0) {
            out[0] = 1.f - (float)(sm[0] / (double)NVOX);
            g_ctr = 0;   // reset for next graph replay
        }
    }
}

extern "C" void kernel_launch(void* const* d_in, const int* in_sizes, int n_in,
                              void* d_out, int out_size) {
    const float* p = (const float*)d_in[0];
    const float* t = (const float*)d_in[1];
    float* out = (float*)d_out;

    passW<<<4000, 256>>>(p, t);     // 1,024,000 threads
    passD<<<500, 256>>>();          //   128,000 threads (8 voxels/step)
    passH<<<NPART, 128>>>(out);     //   256,000 threads + folded reduce
}

// round 15
// speedup vs baseline: 1.2197x; 1.1561x over previous
#include <cuda_runtime.h>
#include <cuda_fp16.h>

#define DD 160
#define HH 160
#define WW 160
#define NB 2
#define HW_ (HH * WW)
#define DHW_ (DD * HH * WW)          // 4,096,000
#define NVOX (NB * DHW_)             // 8,192,000
#define DCH 4
#define DL  (DD / DCH)               // 40
#define HCH 10
#define HL  (HH / HCH)               // 16
#define NPART 2000                   // passH blocks

#define G0c 0.0125602f
#define G1c 0.0788279f
#define G2c 0.2372961f
#define G3c 0.3426315f

typedef unsigned long long u64;

__device__ __forceinline__ float gk(int k) {
    constexpr float g[7] = {G0c, G1c, G2c, G3c, G2c, G1c, G0c};
    return g[k];
}
__device__ __forceinline__ u64 pk(float lo, float hi) {
    u64 r; asm("mov.b64 %0, {%1, %2};" : "=l"(r) : "f"(lo), "f"(hi)); return r;
}
__device__ __forceinline__ float2 upk(u64 v) {
    float2 r; asm("mov.b64 {%0, %1}, %2;" : "=f"(r.x), "=f"(r.y) : "l"(v)); return r;
}
__device__ __forceinline__ u64 fma2(u64 a, u64 b, u64 c) {
    u64 d; asm("fma.rn.f32x2 %0, %1, %2, %3;" : "=l"(d) : "l"(a), "l"(b), "l"(c)); return d;
}
__device__ __forceinline__ u64 mul2(u64 a, u64 b) {
    u64 d; asm("mul.rn.f32x2 %0, %1, %2;" : "=l"(d) : "l"(a), "l"(b)); return d;
}
__device__ __forceinline__ u64 add2(u64 a, u64 b) {
    u64 d; asm("add.rn.f32x2 %0, %1, %2;" : "=l"(d) : "l"(a), "l"(b)); return d;
}
__device__ __forceinline__ unsigned h2u(__half2 h) {
    return *reinterpret_cast<unsigned*>(&h);
}

// zero-padding valid-weight factor per axis
__device__ __forceinline__ float bfac(int i) {
    float f = 1.f;
    if (i < 3)   f -= (i == 2 ? G0c : (i == 1 ? (G0c + G1c) : (G0c + G1c + G2c)));
    if (i > 156) f -= (i == 157 ? G0c : (i == 158 ? (G0c + G1c) : (G0c + G1c + G2c)));
    return f;
}

// 4 shifted fields {q, r, u=q^2+r^2, qr} x 2 batches (65.5 MB each buffer)
// g_buf : planar [vol=f*NB+n][d][h][w] fp16 (passW out / passD in)
// g_buf2: field-interleaved [n][d][h][f(4)][80*half2] fp16 (passD out / passH in)
__device__ __half g_buf[8u * DHW_];
__device__ __half g_buf2[8u * DHW_];
__device__ float g_partials[NPART];
__device__ int g_ctr;

// ---------------------------------------------------------------------------
// passW: 7-tap W-conv of 4 shifted fields {q,r,u,qr}, q=p-1/2, u=q^2+r^2.
// Thread owns an 8-wide w-octet. Scatter form with FFMA-imm.
// ---------------------------------------------------------------------------
__global__ void __launch_bounds__(256) passW(const float* __restrict__ p,
                                             const float* __restrict__ t) {
    int tid = blockIdx.x * blockDim.x + threadIdx.x;   // 1,024,000
    int oct = tid % 20;
    int rem = tid / 20;
    int h   = rem % HH;
    int rm2 = rem / HH;
    int d   = rm2 % DD;
    int n   = rm2 / DD;
    int w0  = oct * 8;

    long rb = (long)n * DHW_ + ((long)d * HH + h) * WW + w0;
    const float4* p4 = (const float4*)(p + rb - 4);
    const float4* t4 = (const float4*)(t + rb - 4);
    const float4 z4 = {0.f, 0.f, 0.f, 0.f};

    float4 a0 = (oct > 0)  ? p4[0] : z4;
    float4 a1 = p4[1];
    float4 a2 = p4[2];
    float4 a3 = (oct < 19) ? p4[3] : z4;
    float4 b0 = (oct > 0)  ? t4[0] : z4;
    float4 b1 = t4[1];
    float4 b2 = t4[2];
    float4 b3 = (oct < 19) ? t4[3] : z4;

    float q[16], r[16];
    q[0]=0.f;       q[1]=a0.y-0.5f; q[2]=a0.z-0.5f; q[3]=a0.w-0.5f;
    q[4]=a1.x-0.5f; q[5]=a1.y-0.5f; q[6]=a1.z-0.5f; q[7]=a1.w-0.5f;
    q[8]=a2.x-0.5f; q[9]=a2.y-0.5f; q[10]=a2.z-0.5f; q[11]=a2.w-0.5f;
    q[12]=a3.x-0.5f; q[13]=a3.y-0.5f; q[14]=a3.z-0.5f; q[15]=0.f;
    r[0]=0.f;       r[1]=b0.y-0.5f; r[2]=b0.z-0.5f; r[3]=b0.w-0.5f;
    r[4]=b1.x-0.5f; r[5]=b1.y-0.5f; r[6]=b1.z-0.5f; r[7]=b1.w-0.5f;
    r[8]=b2.x-0.5f; r[9]=b2.y-0.5f; r[10]=b2.z-0.5f; r[11]=b2.w-0.5f;
    r[12]=b3.x-0.5f; r[13]=b3.y-0.5f; r[14]=b3.z-0.5f; r[15]=0.f;

    if (oct == 0)  { q[1]=q[2]=q[3]=0.f;    r[1]=r[2]=r[3]=0.f; }
    if (oct == 19) { q[12]=q[13]=q[14]=0.f; r[12]=r[13]=r[14]=0.f; }

    float c0[8], c1[8], c2[8], c3[8];
#pragma unroll
    for (int j = 0; j < 8; ++j) { c0[j]=0.f; c1[j]=0.f; c2[j]=0.f; c3[j]=0.f; }

#pragma unroll
    for (int i = 1; i < 15; ++i) {
        float qi = q[i], ri = r[i];
        float uu = fmaf(ri, ri, qi * qi);   // q^2 + r^2
        float pr = qi * ri;
#pragma unroll
        for (int j = 0; j < 8; ++j) {
            const int k = i - 1 - j;
            if (k >= 0 && k < 7) {
                const float g = gk(k);
                c0[j] = fmaf(g, qi, c0[j]);
                c1[j] = fmaf(g, ri, c1[j]);
                c2[j] = fmaf(g, uu, c2[j]);
                c3[j] = fmaf(g, pr, c3[j]);
            }
        }
    }

    long ob = rb / 8;
    uint4* outv = (uint4*)g_buf;
    {
        uint4 v;
        v.x = h2u(__floats2half2_rn(c0[0], c0[1]));
        v.y = h2u(__floats2half2_rn(c0[2], c0[3]));
        v.z = h2u(__floats2half2_rn(c0[4], c0[5]));
        v.w = h2u(__floats2half2_rn(c0[6], c0[7]));
        outv[(long)(0 * NB) * (DHW_ / 8) + ob] = v;
        v.x = h2u(__floats2half2_rn(c1[0], c1[1]));
        v.y = h2u(__floats2half2_rn(c1[2], c1[3]));
        v.z = h2u(__floats2half2_rn(c1[4], c1[5]));
        v.w = h2u(__floats2half2_rn(c1[6], c1[7]));
        outv[(long)(1 * NB) * (DHW_ / 8) + ob] = v;
        v.x = h2u(__floats2half2_rn(c2[0], c2[1]));
        v.y = h2u(__floats2half2_rn(c2[2], c2[3]));
        v.z = h2u(__floats2half2_rn(c2[4], c2[5]));
        v.w = h2u(__floats2half2_rn(c2[6], c2[7]));
        outv[(long)(2 * NB) * (DHW_ / 8) + ob] = v;
        v.x = h2u(__floats2half2_rn(c3[0], c3[1]));
        v.y = h2u(__floats2half2_rn(c3[2], c3[3]));
        v.z = h2u(__floats2half2_rn(c3[4], c3[5]));
        v.w = h2u(__floats2half2_rn(c3[6], c3[7]));
        outv[(long)(3 * NB) * (DHW_ / 8) + ob] = v;
    }
}

// ---------------------------------------------------------------------------
// passD: streaming 7-tap D-conv in HFMA2, 8 voxels (uint4) per thread-step.
// Reads planar g_buf (8 vols); writes field-interleaved g_buf2.
// ---------------------------------------------------------------------------
__global__ void __launch_bounds__(256) passD() {
    int tid = blockIdx.x * blockDim.x + threadIdx.x;   // 102,400
    int wq  = tid % 20;
    int rem = tid / 20;
    int ci  = rem % DCH;
    int rm2 = rem / DCH;
    int h   = rm2 % HH;
    int vol = rm2 / HH;                 // 0..7
    int d0  = ci * DL;
    int f   = vol >> 1;                 // vol = f*NB + n
    int n   = vol & 1;

    const uint4* src = (const uint4*)g_buf + (long)vol * (DHW_ / 8) + (long)h * 20 + wq;
    // interleaved dst (uint4): ((n*DD + d)*HH + h)*80 + f*20 + wq
    uint4* dst = (uint4*)g_buf2 + (((long)n * DD + d0) * HH + h) * 80 + f * 20 + wq;
    const int DS  = HW_ / 8;            // src d-stride (uint4) = 3200
    const int DSO = HH * 80;            // dst d-stride (uint4) = 12800

    const __half2 Z = __float2half2_rn(0.f);
    const __half2 G0h = __float2half2_rn(G0c), G1h = __float2half2_rn(G1c);
    const __half2 G2h = __float2half2_rn(G2c), G3h = __float2half2_rn(G3c);

    __half2 w0[7], w1[7], w2[7], w3[7];
#pragma unroll
    for (int k = 0; k < 7; ++k) {
        int dd = d0 - 3 + k;
        if (dd >= 0 && dd < DD) {
            uint4 v = src[(long)dd * DS];
            w0[k] = *(__half2*)&v.x; w1[k] = *(__half2*)&v.y;
            w2[k] = *(__half2*)&v.z; w3[k] = *(__half2*)&v.w;
        } else { w0[k] = Z; w1[k] = Z; w2[k] = Z; w3[k] = Z; }
    }

    const uint4* sp = src + (long)(d0 + 4) * DS;

#pragma unroll 4
    for (int i = 0; i < DL; ++i) {
        int dn = d0 + i + 4;
        __half2 n0 = Z, n1 = Z, n2 = Z, n3 = Z;
        if (dn < DD) {
            uint4 v = *sp;
            n0 = *(__half2*)&v.x; n1 = *(__half2*)&v.y;
            n2 = *(__half2*)&v.z; n3 = *(__half2*)&v.w;
        }
        __half2 y0 = __hmul2(G0h, w0[0]);
        __half2 y1 = __hmul2(G0h, w1[0]);
        __half2 y2 = __hmul2(G0h, w2[0]);
        __half2 y3 = __hmul2(G0h, w3[0]);
        y0 = __hfma2(G1h, w0[1], y0); y1 = __hfma2(G1h, w1[1], y1);
        y2 = __hfma2(G1h, w2[1], y2); y3 = __hfma2(G1h, w3[1], y3);
        y0 = __hfma2(G2h, w0[2], y0); y1 = __hfma2(G2h, w1[2], y1);
        y2 = __hfma2(G2h, w2[2], y2); y3 = __hfma2(G2h, w3[2], y3);
        y0 = __hfma2(G3h, w0[3], y0); y1 = __hfma2(G3h, w1[3], y1);
        y2 = __hfma2(G3h, w2[3], y2); y3 = __hfma2(G3h, w3[3], y3);
        y0 = __hfma2(G2h, w0[4], y0); y1 = __hfma2(G2h, w1[4], y1);
        y2 = __hfma2(G2h, w2[4], y2); y3 = __hfma2(G2h, w3[4], y3);
        y0 = __hfma2(G1h, w0[5], y0); y1 = __hfma2(G1h, w1[5], y1);
        y2 = __hfma2(G1h, w2[5], y2); y3 = __hfma2(G1h, w3[5], y3);
        y0 = __hfma2(G0h, w0[6], y0); y1 = __hfma2(G0h, w1[6], y1);
        y2 = __hfma2(G0h, w2[6], y2); y3 = __hfma2(G0h, w3[6], y3);
        uint4 o;
        o.x = h2u(y0); o.y = h2u(y1); o.z = h2u(y2); o.w = h2u(y3);
        *dst = o;
#pragma unroll
        for (int k = 0; k < 6; ++k) {
            w0[k] = w0[k + 1]; w1[k] = w1[k + 1];
            w2[k] = w2[k + 1]; w3[k] = w3[k + 1];
        }
        w0[6] = n0; w1[6] = n1; w2[6] = n2; w3[6] = n3;
        sp += DS; dst += DSO;
    }
}

// ---------------------------------------------------------------------------
// passH: streaming 7-tap H-conv of 4 fields (HFMA2) with depth-2 prefetch +
// exact border reconstruction + SSIM with one divide per pair + block reduce
// + last-block final reduce. Thread = (n, d, w-pair, h-chunk of 16).
// Interleaved row = 320 half2 (4 fields x 80).
// ---------------------------------------------------------------------------
__global__ void __launch_bounds__(128, 6) passH(float* __restrict__ out) {
    int tid = blockIdx.x * blockDim.x + threadIdx.x;   // 256,000 exactly
    int wp  = tid % 80;
    int rem = tid / 80;
    int ci  = rem % HCH;
    int rm2 = rem / HCH;
    int d   = rm2 % DD;
    int n   = rm2 / DD;
    int h0  = ci * HL;
    int w2  = 2 * wp;

    const __half2 Z = __float2half2_rn(0.f);
    const __half2 G0h = __float2half2_rn(G0c), G1h = __float2half2_rn(G1c);
    const __half2 G2h = __float2half2_rn(G2c), G3h = __float2half2_rn(G3c);
    const u64 K05 = pk(0.5f,0.5f), Kn025 = pk(-0.25f,-0.25f), K2 = pk(2.f,2.f);
    const u64 KC1 = pk(1e-4f,1e-4f), KC2 = pk(9e-4f,9e-4f), Kn1 = pk(-1.f,-1.f);
    const u64 Kn2 = pk(-2.f,-2.f), Kn05 = pk(-0.5f,-0.5f);

    float bd = bfac(d);
    u64 wwp = pk(bd * bfac(w2), bd * bfac(w2 + 1));

    // row r, field f at: base + r*320 + f*80  (half2 units)
    const __half2* base = (const __half2*)g_buf2 +
                          (((long)n * DD + d) * HH) * 320 + wp;

    __half2 win[4][7];
#pragma unroll
    for (int k = 0; k < 7; ++k) {
        int row = h0 - 3 + k;
        bool v = (row >= 0) && (row < HH);
        const __half2* rp = base + (long)(v ? row : 0) * 320;
#pragma unroll
        for (int f = 0; f < 4; ++f)
            win[f][k] = v ? rp[f * 80] : Z;
    }

    // depth-2 prefetch: P1 = row h0+4, P2 = row h0+5
    __half2 P1[4], P2[4];
    {
        bool v1 = (h0 + 4 < HH), v2 = (h0 + 5 < HH);
        const __half2* r1 = base + (long)(v1 ? h0 + 4 : 0) * 320;
        const __half2* r2 = base + (long)(v2 ? h0 + 5 : 0) * 320;
#pragma unroll
        for (int f = 0; f < 4; ++f) {
            P1[f] = v1 ? r1[f * 80] : Z;
            P2[f] = v2 ? r2[f * 80] : Z;
        }
    }

    float acc_ssim = 0.f;

#pragma unroll 4
    for (int i = 0; i < HL; ++i) {
        int h = h0 + i;

        u64 c[4];
#pragma unroll
        for (int f = 0; f < 4; ++f) {
            __half2 y = __hmul2(G0h, win[f][0]);
            y = __hfma2(G1h, win[f][1], y);
            y = __hfma2(G2h, win[f][2], y);
            y = __hfma2(G3h, win[f][3], y);
            y = __hfma2(G2h, win[f][4], y);
            y = __hfma2(G1h, win[f][5], y);
            y = __hfma2(G0h, win[f][6], y);
            float2 cf = __half22float2(y);
            c[f] = pk(cf.x, cf.y);
        }

        float bh = bfac(h);
        u64 W2   = mul2(wwp, pk(bh, bh));
        u64 mu1  = fma2(W2, K05, c[0]);
        u64 mu2  = fma2(W2, K05, c[1]);
        u64 S    = add2(mu1, mu2);                       // mu1+mu2
        u64 mu12 = mul2(mu1, mu2);
        u64 A    = fma2(mu12, Kn2, mul2(S, S));          // mu1^2+mu2^2
        u64 Ept  = fma2(S, K05, fma2(W2, Kn025, c[3]));  // E[pt]
        u64 s12  = fma2(mu12, Kn1, Ept);
        u64 E2   = fma2(W2, Kn05, add2(c[2], S));        // E[p^2]+E[t^2]
        u64 sden = add2(fma2(A, Kn1, E2), KC2);          // s1+s2+C2
        u64 den  = mul2(add2(A, KC1), sden);
        u64 num  = mul2(fma2(mu12, K2, KC1), fma2(s12, K2, KC2));
        float2 nf = upk(num), df = upk(den);
        float tnum = fmaf(nf.x, df.y, nf.y * df.x);
        acc_ssim += __fdividef(tnum, df.x * df.y);

        // shift window, insert P1; P1 <- P2; issue P2 load (row h+6)
        bool v = (h + 6 < HH);
        const __half2* rp = base + (long)(v ? h + 6 : 0) * 320;
#pragma unroll
        for (int f = 0; f < 4; ++f) {
#pragma unroll
            for (int k = 0; k < 6; ++k) win[f][k] = win[f][k + 1];
            win[f][6] = P1[f];
            P1[f] = P2[f];
            P2[f] = v ? rp[f * 80] : Z;
        }
    }

    __shared__ float sred[128];
    __shared__ bool is_last;
    int lt = threadIdx.x;
    sred[lt] = acc_ssim;
    __syncthreads();
    for (int s = 64; s > 0; s >>= 1) {
        if (lt < s) sred[lt] += sred[lt + s];
        __syncthreads();
    }
    if (lt == 0) {
        g_partials[blockIdx.x] = sred[0];
        __threadfence();
        int v = atomicAdd(&g_ctr, 1);
        is_last = (v == (int)gridDim.x - 1);
    }
    __syncthreads();

    if (is_last) {
        __shared__ double sm[128];
        double acc = 0.0;
        for (int i = lt; i < NPART; i += 128) acc += (double)g_partials[i];
        sm[lt] = acc;
        __syncthreads();
        for (int s = 64; s > 0; s >>= 1) {
            if (lt < s) sm[lt] += sm[lt + s];
            __syncthreads();
        }
        if (lt == 0) {
            out[0] = 1.f - (float)(sm[0] / (double)NVOX);
            g_ctr = 0;   // reset for next graph replay
        }
    }
}

extern "C" void kernel_launch(void* const* d_in, const int* in_sizes, int n_in,
                              void* d_out, int out_size) {
    const float* p = (const float*)d_in[0];
    const float* t = (const float*)d_in[1];
    float* out = (float*)d_out;

    passW<<<4000, 256>>>(p, t);     // 1,024,000 threads
    passD<<<400, 256>>>();          //   102,400 threads (8 voxels/step, 8 vols)
    passH<<<NPART, 128>>>(out);     //   256,000 threads + folded reduce
}

// round 16
// speedup vs baseline: 1.2516x; 1.0261x over previous
#include <cuda_runtime.h>
#include <cuda_fp16.h>

#define DD 160
#define HH 160
#define WW 160
#define NB 2
#define HW_ (HH * WW)
#define DHW_ (DD * HH * WW)          // 4,096,000
#define NVOX (NB * DHW_)             // 8,192,000
#define DCH 4
#define DL  (DD / DCH)               // 40
#define HCH 10
#define HL  (HH / HCH)               // 16
#define NPART 2000                   // passH blocks

#define G0c 0.0125602f
#define G1c 0.0788279f
#define G2c 0.2372961f
#define G3c 0.3426315f

typedef unsigned long long u64;

__device__ __forceinline__ float gk(int k) {
    constexpr float g[7] = {G0c, G1c, G2c, G3c, G2c, G1c, G0c};
    return g[k];
}
__device__ __forceinline__ u64 pk(float lo, float hi) {
    u64 r; asm("mov.b64 %0, {%1, %2};" : "=l"(r) : "f"(lo), "f"(hi)); return r;
}
__device__ __forceinline__ float2 upk(u64 v) {
    float2 r; asm("mov.b64 {%0, %1}, %2;" : "=f"(r.x), "=f"(r.y) : "l"(v)); return r;
}
__device__ __forceinline__ u64 fma2(u64 a, u64 b, u64 c) {
    u64 d; asm("fma.rn.f32x2 %0, %1, %2, %3;" : "=l"(d) : "l"(a), "l"(b), "l"(c)); return d;
}
__device__ __forceinline__ u64 mul2(u64 a, u64 b) {
    u64 d; asm("mul.rn.f32x2 %0, %1, %2;" : "=l"(d) : "l"(a), "l"(b)); return d;
}
__device__ __forceinline__ u64 add2(u64 a, u64 b) {
    u64 d; asm("add.rn.f32x2 %0, %1, %2;" : "=l"(d) : "l"(a), "l"(b)); return d;
}
__device__ __forceinline__ unsigned h2u(__half2 h) {
    return *reinterpret_cast<unsigned*>(&h);
}

// zero-padding valid-weight factor per axis
__device__ __forceinline__ float bfac(int i) {
    float f = 1.f;
    if (i < 3)   f -= (i == 2 ? G0c : (i == 1 ? (G0c + G1c) : (G0c + G1c + G2c)));
    if (i > 156) f -= (i == 157 ? G0c : (i == 158 ? (G0c + G1c) : (G0c + G1c + G2c)));
    return f;
}

// 4 shifted fields {q, r, u=q^2+r^2, qr} x 2 batches (65.5 MB each buffer)
__device__ __half g_buf[8u * DHW_];
__device__ __half g_buf2[8u * DHW_];
__device__ float g_partials[NPART];
__device__ int g_ctr;

// ---------------------------------------------------------------------------
// passW: 7-tap W-conv of 4 shifted fields {q,r,u,qr}. (R15-proven)
// ---------------------------------------------------------------------------
__global__ void __launch_bounds__(256) passW(const float* __restrict__ p,
                                             const float* __restrict__ t) {
    int tid = blockIdx.x * blockDim.x + threadIdx.x;   // 1,024,000
    int oct = tid % 20;
    int rem = tid / 20;
    int h   = rem % HH;
    int rm2 = rem / HH;
    int d   = rm2 % DD;
    int n   = rm2 / DD;
    int w0  = oct * 8;

    long rb = (long)n * DHW_ + ((long)d * HH + h) * WW + w0;
    const float4* p4 = (const float4*)(p + rb - 4);
    const float4* t4 = (const float4*)(t + rb - 4);
    const float4 z4 = {0.f, 0.f, 0.f, 0.f};

    float4 a0 = (oct > 0)  ? p4[0] : z4;
    float4 a1 = p4[1];
    float4 a2 = p4[2];
    float4 a3 = (oct < 19) ? p4[3] : z4;
    float4 b0 = (oct > 0)  ? t4[0] : z4;
    float4 b1 = t4[1];
    float4 b2 = t4[2];
    float4 b3 = (oct < 19) ? t4[3] : z4;

    float q[16], r[16];
    q[0]=0.f;       q[1]=a0.y-0.5f; q[2]=a0.z-0.5f; q[3]=a0.w-0.5f;
    q[4]=a1.x-0.5f; q[5]=a1.y-0.5f; q[6]=a1.z-0.5f; q[7]=a1.w-0.5f;
    q[8]=a2.x-0.5f; q[9]=a2.y-0.5f; q[10]=a2.z-0.5f; q[11]=a2.w-0.5f;
    q[12]=a3.x-0.5f; q[13]=a3.y-0.5f; q[14]=a3.z-0.5f; q[15]=0.f;
    r[0]=0.f;       r[1]=b0.y-0.5f; r[2]=b0.z-0.5f; r[3]=b0.w-0.5f;
    r[4]=b1.x-0.5f; r[5]=b1.y-0.5f; r[6]=b1.z-0.5f; r[7]=b1.w-0.5f;
    r[8]=b2.x-0.5f; r[9]=b2.y-0.5f; r[10]=b2.z-0.5f; r[11]=b2.w-0.5f;
    r[12]=b3.x-0.5f; r[13]=b3.y-0.5f; r[14]=b3.z-0.5f; r[15]=0.f;

    if (oct == 0)  { q[1]=q[2]=q[3]=0.f;    r[1]=r[2]=r[3]=0.f; }
    if (oct == 19) { q[12]=q[13]=q[14]=0.f; r[12]=r[13]=r[14]=0.f; }

    float c0[8], c1[8], c2[8], c3[8];
#pragma unroll
    for (int j = 0; j < 8; ++j) { c0[j]=0.f; c1[j]=0.f; c2[j]=0.f; c3[j]=0.f; }

#pragma unroll
    for (int i = 1; i < 15; ++i) {
        float qi = q[i], ri = r[i];
        float uu = fmaf(ri, ri, qi * qi);
        float pr = qi * ri;
#pragma unroll
        for (int j = 0; j < 8; ++j) {
            const int k = i - 1 - j;
            if (k >= 0 && k < 7) {
                const float g = gk(k);
                c0[j] = fmaf(g, qi, c0[j]);
                c1[j] = fmaf(g, ri, c1[j]);
                c2[j] = fmaf(g, uu, c2[j]);
                c3[j] = fmaf(g, pr, c3[j]);
            }
        }
    }

    long ob = rb / 8;
    uint4* outv = (uint4*)g_buf;
    {
        uint4 v;
        v.x = h2u(__floats2half2_rn(c0[0], c0[1]));
        v.y = h2u(__floats2half2_rn(c0[2], c0[3]));
        v.z = h2u(__floats2half2_rn(c0[4], c0[5]));
        v.w = h2u(__floats2half2_rn(c0[6], c0[7]));
        outv[(long)(0 * NB) * (DHW_ / 8) + ob] = v;
        v.x = h2u(__floats2half2_rn(c1[0], c1[1]));
        v.y = h2u(__floats2half2_rn(c1[2], c1[3]));
        v.z = h2u(__floats2half2_rn(c1[4], c1[5]));
        v.w = h2u(__floats2half2_rn(c1[6], c1[7]));
        outv[(long)(1 * NB) * (DHW_ / 8) + ob] = v;
        v.x = h2u(__floats2half2_rn(c2[0], c2[1]));
        v.y = h2u(__floats2half2_rn(c2[2], c2[3]));
        v.z = h2u(__floats2half2_rn(c2[4], c2[5]));
        v.w = h2u(__floats2half2_rn(c2[6], c2[7]));
        outv[(long)(2 * NB) * (DHW_ / 8) + ob] = v;
        v.x = h2u(__floats2half2_rn(c3[0], c3[1]));
        v.y = h2u(__floats2half2_rn(c3[2], c3[3]));
        v.z = h2u(__floats2half2_rn(c3[4], c3[5]));
        v.w = h2u(__floats2half2_rn(c3[6], c3[7]));
        outv[(long)(3 * NB) * (DHW_ / 8) + ob] = v;
    }
}

// ---------------------------------------------------------------------------
// passD: streaming 7-tap D-conv in HFMA2, 8 voxels (uint4) per thread-step.
// Reads planar g_buf (8 vols); writes field-interleaved g_buf2. (R15-proven)
// ---------------------------------------------------------------------------
__global__ void __launch_bounds__(256) passD() {
    int tid = blockIdx.x * blockDim.x + threadIdx.x;   // 102,400
    int wq  = tid % 20;
    int rem = tid / 20;
    int ci  = rem % DCH;
    int rm2 = rem / DCH;
    int h   = rm2 % HH;
    int vol = rm2 / HH;
    int d0  = ci * DL;
    int f   = vol >> 1;
    int n   = vol & 1;

    const uint4* src = (const uint4*)g_buf + (long)vol * (DHW_ / 8) + (long)h * 20 + wq;
    uint4* dst = (uint4*)g_buf2 + (((long)n * DD + d0) * HH + h) * 80 + f * 20 + wq;
    const int DS  = HW_ / 8;
    const int DSO = HH * 80;

    const __half2 Z = __float2half2_rn(0.f);
    const __half2 G0h = __float2half2_rn(G0c), G1h = __float2half2_rn(G1c);
    const __half2 G2h = __float2half2_rn(G2c), G3h = __float2half2_rn(G3c);

    __half2 w0[7], w1[7], w2[7], w3[7];
#pragma unroll
    for (int k = 0; k < 7; ++k) {
        int dd = d0 - 3 + k;
        if (dd >= 0 && dd < DD) {
            uint4 v = src[(long)dd * DS];
            w0[k] = *(__half2*)&v.x; w1[k] = *(__half2*)&v.y;
            w2[k] = *(__half2*)&v.z; w3[k] = *(__half2*)&v.w;
        } else { w0[k] = Z; w1[k] = Z; w2[k] = Z; w3[k] = Z; }
    }

    const uint4* sp = src + (long)(d0 + 4) * DS;

#pragma unroll 4
    for (int i = 0; i < DL; ++i) {
        int dn = d0 + i + 4;
        __half2 n0 = Z, n1 = Z, n2 = Z, n3 = Z;
        if (dn < DD) {
            uint4 v = *sp;
            n0 = *(__half2*)&v.x; n1 = *(__half2*)&v.y;
            n2 = *(__half2*)&v.z; n3 = *(__half2*)&v.w;
        }
        __half2 y0 = __hmul2(G0h, w0[0]);
        __half2 y1 = __hmul2(G0h, w1[0]);
        __half2 y2 = __hmul2(G0h, w2[0]);
        __half2 y3 = __hmul2(G0h, w3[0]);
        y0 = __hfma2(G1h, w0[1], y0); y1 = __hfma2(G1h, w1[1], y1);
        y2 = __hfma2(G1h, w2[1], y2); y3 = __hfma2(G1h, w3[1], y3);
        y0 = __hfma2(G2h, w0[2], y0); y1 = __hfma2(G2h, w1[2], y1);
        y2 = __hfma2(G2h, w2[2], y2); y3 = __hfma2(G2h, w3[2], y3);
        y0 = __hfma2(G3h, w0[3], y0); y1 = __hfma2(G3h, w1[3], y1);
        y2 = __hfma2(G3h, w2[3], y2); y3 = __hfma2(G3h, w3[3], y3);
        y0 = __hfma2(G2h, w0[4], y0); y1 = __hfma2(G2h, w1[4], y1);
        y2 = __hfma2(G2h, w2[4], y2); y3 = __hfma2(G2h, w3[4], y3);
        y0 = __hfma2(G1h, w0[5], y0); y1 = __hfma2(G1h, w1[5], y1);
        y2 = __hfma2(G1h, w2[5], y2); y3 = __hfma2(G1h, w3[5], y3);
        y0 = __hfma2(G0h, w0[6], y0); y1 = __hfma2(G0h, w1[6], y1);
        y2 = __hfma2(G0h, w2[6], y2); y3 = __hfma2(G0h, w3[6], y3);
        uint4 o;
        o.x = h2u(y0); o.y = h2u(y1); o.z = h2u(y2); o.w = h2u(y3);
        *dst = o;
#pragma unroll
        for (int k = 0; k < 6; ++k) {
            w0[k] = w0[k + 1]; w1[k] = w1[k + 1];
            w2[k] = w2[k + 1]; w3[k] = w3[k + 1];
        }
        w0[6] = n0; w1[6] = n1; w2[6] = n2; w3[6] = n3;
        sp += DS; dst += DSO;
    }
}

// ---------------------------------------------------------------------------
// passH: FULLY UNROLLED streaming 7-tap H-conv of 4 fields + SSIM.
// Full unroll of the HL=16 loop lets ptxas rename the rolling window — the
// 24 shift MOVs per iteration vanish. (Otherwise identical to R15.)
// ---------------------------------------------------------------------------
__global__ void __launch_bounds__(128, 6) passH(float* __restrict__ out) {
    int tid = blockIdx.x * blockDim.x + threadIdx.x;   // 256,000 exactly
    int wp  = tid % 80;
    int rem = tid / 80;
    int ci  = rem % HCH;
    int rm2 = rem / HCH;
    int d   = rm2 % DD;
    int n   = rm2 / DD;
    int h0  = ci * HL;
    int w2  = 2 * wp;

    const __half2 Z = __float2half2_rn(0.f);
    const __half2 G0h = __float2half2_rn(G0c), G1h = __float2half2_rn(G1c);
    const __half2 G2h = __float2half2_rn(G2c), G3h = __float2half2_rn(G3c);
    const u64 K05 = pk(0.5f,0.5f), Kn025 = pk(-0.25f,-0.25f), K2 = pk(2.f,2.f);
    const u64 KC1 = pk(1e-4f,1e-4f), KC2 = pk(9e-4f,9e-4f), Kn1 = pk(-1.f,-1.f);
    const u64 Kn2 = pk(-2.f,-2.f), Kn05 = pk(-0.5f,-0.5f);

    float bd = bfac(d);
    u64 wwp = pk(bd * bfac(w2), bd * bfac(w2 + 1));

    const __half2* base = (const __half2*)g_buf2 +
                          (((long)n * DD + d) * HH) * 320 + wp;

    __half2 win[4][7];
#pragma unroll
    for (int k = 0; k < 7; ++k) {
        int row = h0 - 3 + k;
        bool v = (row >= 0) && (row < HH);
        const __half2* rp = base + (long)(v ? row : 0) * 320;
#pragma unroll
        for (int f = 0; f < 4; ++f)
            win[f][k] = v ? rp[f * 80] : Z;
    }

    __half2 P1[4], P2[4];
    {
        bool v1 = (h0 + 4 < HH), v2 = (h0 + 5 < HH);
        const __half2* r1 = base + (long)(v1 ? h0 + 4 : 0) * 320;
        const __half2* r2 = base + (long)(v2 ? h0 + 5 : 0) * 320;
#pragma unroll
        for (int f = 0; f < 4; ++f) {
            P1[f] = v1 ? r1[f * 80] : Z;
            P2[f] = v2 ? r2[f * 80] : Z;
        }
    }

    float acc_ssim = 0.f;

#pragma unroll
    for (int i = 0; i < HL; ++i) {
        int h = h0 + i;

        u64 c[4];
#pragma unroll
        for (int f = 0; f < 4; ++f) {
            __half2 y = __hmul2(G0h, win[f][0]);
            y = __hfma2(G1h, win[f][1], y);
            y = __hfma2(G2h, win[f][2], y);
            y = __hfma2(G3h, win[f][3], y);
            y = __hfma2(G2h, win[f][4], y);
            y = __hfma2(G1h, win[f][5], y);
            y = __hfma2(G0h, win[f][6], y);
            float2 cf = __half22float2(y);
            c[f] = pk(cf.x, cf.y);
        }

        float bh = bfac(h);
        u64 W2   = mul2(wwp, pk(bh, bh));
        u64 mu1  = fma2(W2, K05, c[0]);
        u64 mu2  = fma2(W2, K05, c[1]);
        u64 S    = add2(mu1, mu2);
        u64 mu12 = mul2(mu1, mu2);
        u64 A    = fma2(mu12, Kn2, mul2(S, S));
        u64 Ept  = fma2(S, K05, fma2(W2, Kn025, c[3]));
        u64 s12  = fma2(mu12, Kn1, Ept);
        u64 E2   = fma2(W2, Kn05, add2(c[2], S));
        u64 sden = add2(fma2(A, Kn1, E2), KC2);
        u64 den  = mul2(add2(A, KC1), sden);
        u64 num  = mul2(fma2(mu12, K2, KC1), fma2(s12, K2, KC2));
        float2 nf = upk(num), df = upk(den);
        float tnum = fmaf(nf.x, df.y, nf.y * df.x);
        acc_ssim += __fdividef(tnum, df.x * df.y);

        bool v = (h + 6 < HH);
        const __half2* rp = base + (long)(v ? h + 6 : 0) * 320;
#pragma unroll
        for (int f = 0; f < 4; ++f) {
#pragma unroll
            for (int k = 0; k < 6; ++k) win[f][k] = win[f][k + 1];
            win[f][6] = P1[f];
            P1[f] = P2[f];
            P2[f] = v ? rp[f * 80] : Z;
        }
    }

    __shared__ float sred[128];
    __shared__ bool is_last;
    int lt = threadIdx.x;
    sred[lt] = acc_ssim;
    __syncthreads();
    for (int s = 64; s > 0; s >>= 1) {
        if (lt < s) sred[lt] += sred[lt + s];
        __syncthreads();
    }
    if (lt == 0) {
        g_partials[blockIdx.x] = sred[0];
        __threadfence();
        int v = atomicAdd(&g_ctr, 1);
        is_last = (v == (int)gridDim.x - 1);
    }
    __syncthreads();

    if (is_last) {
        __shared__ double sm[128];
        double acc = 0.0;
        for (int i = lt; i < NPART; i += 128) acc += (double)g_partials[i];
        sm[lt] = acc;
        __syncthreads();
        for (int s = 64; s > 0; s >>= 1) {
            if (lt < s) sm[lt] += sm[lt + s];
            __syncthreads();
        }
        if (lt == 0) {
            out[0] = 1.f - (float)(sm[0] / (double)NVOX);
            g_ctr = 0;   // reset for next graph replay
        }
    }
}

extern "C" void kernel_launch(void* const* d_in, const int* in_sizes, int n_in,
                              void* d_out, int out_size) {
    const float* p = (const float*)d_in[0];
    const float* t = (const float*)d_in[1];
    float* out = (float*)d_out;

    passW<<<4000, 256>>>(p, t);     // 1,024,000 threads
    passD<<<400, 256>>>();          //   102,400 threads (8 voxels/step)
    passH<<<NPART, 128>>>(out);     //   256,000 threads + folded reduce
}